// round 6
// baseline (speedup 1.0000x reference)
#include <cuda_runtime.h>
#include <cuda_bf16.h>
#include <cstdint>
#include <float.h>

#define NQ    8
#define BINS  1024
#define DIM   256
#define BB    16
#define TT    1500
#define NN    (BB * TT)
#define NPAD  24064
#define NTILE 188

// device scratch
__device__ float g_res[NPAD * DIM];          // residual, D-permuted within 8-groups
__device__ float g_acc[NPAD * DIM];          // natural D order
__device__ float g_cbp[NQ * BINS * DIM];     // permuted codebook copy
__device__ int   g_cand[NPAD * 32];
__device__ float g_cand_s[NPAD * 32];
__device__ float g_cbsq[NQ * BINS];
__device__ float g_partial[NQ * NN];

// D permutation within each 8-group
__device__ __forceinline__ int permD(int o) { return (o & ~7) | ((o & 3) << 1) | ((o & 4) >> 2); }
__device__ __forceinline__ int invD(int p)  { return (p & ~7) | ((p & 1) << 2) | ((p & 6) >> 1); }

// ---------------- helpers ----------------
__device__ __forceinline__ uint32_t smem_u32(const void* p) {
    uint32_t a;
    asm("{ .reg .u64 t; cvta.to.shared.u64 t, %1; cvt.u32.u64 %0, t; }" : "=r"(a) : "l"(p));
    return a;
}
__device__ __forceinline__ void cp_async16(uint32_t dst, const void* src) {
    asm volatile("cp.async.cg.shared.global [%0], [%1], 16;" :: "r"(dst), "l"(src) : "memory");
}
#define CP_COMMIT() asm volatile("cp.async.commit_group;" ::: "memory")
#define CP_WAIT2()  asm volatile("cp.async.wait_group 2;" ::: "memory")

__device__ __forceinline__ void mma_tf32(float* c, const uint32_t* a, const uint32_t* b) {
    asm volatile(
        "mma.sync.aligned.m16n8k8.row.col.f32.tf32.tf32.f32 "
        "{%0,%1,%2,%3}, {%4,%5,%6,%7}, {%8,%9}, {%0,%1,%2,%3};"
        : "+f"(c[0]), "+f"(c[1]), "+f"(c[2]), "+f"(c[3])
        : "r"(a[0]), "r"(a[1]), "r"(a[2]), "r"(a[3]), "r"(b[0]), "r"(b[1]));
}

// smem floats: A[4][128][32] @0 (16384), B[4][64][32] @16384 (8192), cbsq[512] @24576
#define SA(buf, r, c)  (((buf) * 128 + (r)) * 32 + (c))
#define SB(buf, r, c)  (16384 + ((buf) * 64 + (r)) * 32 + (c))
#define SQ(i)          (24576 + (i))
#define SMEM_BYTES     (25088 * 4)

// ---------------- init: x (B,D,T) -> g_res (N, permD) ----------------
__global__ void rvq_init(const float* __restrict__ x) {
    __shared__ float s[32][33];
    int b = blockIdx.z, d0 = blockIdx.y * 32, t0 = blockIdx.x * 32;
    int tx = threadIdx.x, ty = threadIdx.y;
    int t = t0 + tx;
    if (t < TT) s[ty][tx] = x[((size_t)b * DIM + d0 + ty) * TT + t];
    __syncthreads();
    int t2 = t0 + ty;
    if (t2 < TT)
        g_res[((size_t)(b * TT + t2)) * DIM + d0 + permD(tx)] = s[tx][ty];
}

// zero pad rows of g_res only (g_acc handled by q==0 write in select_update)
__global__ void rvq_zero() {
    size_t i = (size_t)NN * DIM + blockIdx.x * blockDim.x + threadIdx.x;
    if (i < (size_t)NPAD * DIM) g_res[i] = 0.0f;
}

// ---------------- cbsq + permuted codebook copy ----------------
__global__ void rvq_cbsq(const float* __restrict__ cb) {
    int warp = (blockIdx.x * blockDim.x + threadIdx.x) >> 5;
    int lane = threadIdx.x & 31;
    if (warp >= NQ * BINS) return;
    const float* row = cb + (size_t)warp * DIM;
    float s = 0.0f;
    for (int d = lane; d < DIM; d += 32) { float c = row[d]; s += c * c; }
    #pragma unroll
    for (int o = 16; o > 0; o >>= 1) s += __shfl_down_sync(0xffffffffu, s, o);
    if (lane == 0) g_cbsq[warp] = s;
}

__global__ void rvq_cbperm(const float* __restrict__ cbs) {
    size_t i = (size_t)blockIdx.x * blockDim.x + threadIdx.x;
    if (i >= (size_t)NQ * BINS * DIM) return;
    int d = (int)(i & 255);
    g_cbp[(i - d) + permD(d)] = cbs[i];
}

// ---------------- tf32 tensor-core argmax: half-tile = 128 rows x 512 bins ----------------
__global__ __launch_bounds__(256, 2) void rvq_argmax_tc(int q) {
    extern __shared__ float sm[];
    const uint32_t sb = smem_u32(sm);
    const int tid = threadIdx.x;
    const int lane = tid & 31, wid = tid >> 5;
    const int gid = lane >> 2, tg = lane & 3;
    const int wm = wid & 3, wn = wid >> 2;        // warp grid 4 (m) x 2 (n)
    const int mtile = blockIdx.x >> 1, half = blockIdx.x & 1;
    const int row0 = mtile * 128;
    const float* __restrict__ cbp = g_cbp + ((size_t)q * BINS + half * 512) * DIM;

    for (int i = tid; i < 512; i += 256) sm[SQ(i)] = g_cbsq[q * BINS + half * 512 + i];

    const int ur = tid >> 3, useg = tid & 7;

    float ts[4][2]; int ti[4][2];
    #pragma unroll
    for (int s = 0; s < 4; s++) {
        ts[s][0] = -FLT_MAX; ts[s][1] = -FLT_MAX;
        ti[s][0] = 0; ti[s][1] = 0;
    }

    // chunk g = nt*8 + kc : A chunk at kof=(g&7)*32, B rows (g>>3)*64, slot g&3
#define PREFETCH_CHUNK(g_) do { \
    const int slot_ = (g_) & 3; \
    const int kof_ = ((g_) & 7) * 32; \
    const int nb_ = ((g_) >> 3) * 64; \
    _Pragma("unroll") \
    for (int i_ = 0; i_ < 4; i_++) { \
        int r_ = ur + i_ * 32; \
        cp_async16(sb + (uint32_t)SA(slot_, r_, (useg ^ (r_ & 7)) * 4) * 4u, \
                   g_res + (size_t)(row0 + r_) * DIM + kof_ + useg * 4); \
    } \
    _Pragma("unroll") \
    for (int i_ = 0; i_ < 2; i_++) { \
        int r_ = ur + i_ * 32; \
        cp_async16(sb + (uint32_t)SB(slot_, r_, (useg ^ (r_ & 7)) * 4) * 4u, \
                   cbp + (size_t)(nb_ + r_) * DIM + kof_ + useg * 4); \
    } \
} while (0)

    // prologue: 3 chunks in flight
    PREFETCH_CHUNK(0); CP_COMMIT();
    PREFETCH_CHUNK(1); CP_COMMIT();
    PREFETCH_CHUNK(2); CP_COMMIT();

    float c[2][4][4];
    #pragma unroll
    for (int mi = 0; mi < 2; mi++)
        #pragma unroll
        for (int ni = 0; ni < 4; ni++)
            #pragma unroll
            for (int v = 0; v < 4; v++) c[mi][ni][v] = 0.0f;

#define FOLD(slot, sc, kg) do { \
    if ((sc) > ts[slot][0]) { \
        ts[slot][1] = ts[slot][0]; ti[slot][1] = ti[slot][0]; \
        ts[slot][0] = (sc); ti[slot][0] = (kg); \
    } else if ((sc) > ts[slot][1]) { ts[slot][1] = (sc); ti[slot][1] = (kg); } \
} while (0)

    #pragma unroll 1
    for (int g = 0; g < 64; g++) {
        CP_WAIT2();            // chunk g landed (pending: g+1, g+2)
        __syncthreads();       // visibility + all warps past chunk g-1
        if (g + 3 < 64) PREFETCH_CHUNK(g + 3);   // overwrites slot (g-1)&3: safe
        CP_COMMIT();           // always commit (empty group at tail keeps counts)

        const int buf = g & 3;
        #pragma unroll
        for (int kk = 0; kk < 4; kk++) {
            const int colp = (((2 * kk + (tg >> 1)) ^ gid) << 2) + 2 * (tg & 1);
            uint32_t a[2][4], b[4][2];
            #pragma unroll
            for (int mi = 0; mi < 2; mi++) {
                int r = wm * 32 + mi * 16 + gid;
                float2 av0 = *(const float2*)&sm[SA(buf, r, colp)];
                float2 av1 = *(const float2*)&sm[SA(buf, r + 8, colp)];
                a[mi][0] = __float_as_uint(av0.x);
                a[mi][1] = __float_as_uint(av1.x);
                a[mi][2] = __float_as_uint(av0.y);
                a[mi][3] = __float_as_uint(av1.y);
            }
            #pragma unroll
            for (int ni = 0; ni < 4; ni++) {
                int n = wn * 32 + ni * 8 + gid;
                float2 bv = *(const float2*)&sm[SB(buf, n, colp)];
                b[ni][0] = __float_as_uint(bv.x);
                b[ni][1] = __float_as_uint(bv.y);
            }
            #pragma unroll
            for (int mi = 0; mi < 2; mi++)
                #pragma unroll
                for (int ni = 0; ni < 4; ni++)
                    mma_tf32(c[mi][ni], a[mi], b[ni]);
        }

        if ((g & 7) == 7) {
            // nt epilogue: fold scores into per-row top-2, reset accums
            const int nt = g >> 3;
            #pragma unroll
            for (int mi = 0; mi < 2; mi++)
                #pragma unroll
                for (int ni = 0; ni < 4; ni++) {
                    int cc = wn * 32 + ni * 8 + tg * 2;
                    int kl = nt * 64 + cc;
                    int kg = half * 512 + kl;
                    float q0 = sm[SQ(kl)], q1 = sm[SQ(kl + 1)];
                    float s0 = 2.0f * c[mi][ni][0] - q0;
                    float s1 = 2.0f * c[mi][ni][1] - q1;
                    float s2 = 2.0f * c[mi][ni][2] - q0;
                    float s3 = 2.0f * c[mi][ni][3] - q1;
                    FOLD(mi * 2 + 0, s0, kg);
                    FOLD(mi * 2 + 0, s1, kg + 1);
                    FOLD(mi * 2 + 1, s2, kg);
                    FOLD(mi * 2 + 1, s3, kg + 1);
                    #pragma unroll
                    for (int v = 0; v < 4; v++) c[mi][ni][v] = 0.0f;
                }
        }
    }

    // write 2 candidates per owned row
    const int owner = wn * 4 + tg;
    #pragma unroll
    for (int s = 0; s < 4; s++) {
        int row = row0 + wm * 32 + (s >> 1) * 16 + gid + (s & 1) * 8;
        size_t base = (size_t)row * 32 + half * 16 + owner * 2;
        g_cand[base]     = ti[s][0];  g_cand_s[base]     = ts[s][0];
        g_cand[base + 1] = ti[s][1];  g_cand_s[base + 1] = ts[s][1];
    }
}

// ---------------- exact select (fp64, margin-filtered) + update ----------------
__global__ void rvq_select_update(const float* __restrict__ cbs,
                                  float* __restrict__ codes_out, int q) {
    __shared__ float sApprox[32];
    __shared__ double sS[32];
    __shared__ int sK;
    __shared__ float red[8];
    __shared__ float sMax;
    const int n = blockIdx.x, tid = threadIdx.x;
    const int w = tid >> 5, lane = tid & 31;
    const float* __restrict__ cb = cbs + (size_t)q * BINS * DIM;

    if (tid < 32) {
        float a = g_cand_s[(size_t)n * 32 + tid];
        sApprox[tid] = a;
        sS[tid] = -1e300;
        #pragma unroll
        for (int o = 16; o > 0; o >>= 1) a = fmaxf(a, __shfl_down_sync(0xffffffffu, a, o));
        if (tid == 0) sMax = a;
    }
    __syncthreads();

    const float thr = sMax - 0.3f;
    #pragma unroll 1
    for (int c4 = 0; c4 < 4; c4++) {
        const int ci = w * 4 + c4;
        if (sApprox[ci] >= thr) {
            const int cand = g_cand[(size_t)n * 32 + ci];
            const float* r = g_res + (size_t)n * DIM;
            const float* c = cb + (size_t)cand * DIM;
            double dot = 0.0, sq = 0.0;
            #pragma unroll
            for (int d = lane; d < DIM; d += 32) {
                double rv = r[d], cv = c[invD(d)];
                dot += rv * cv; sq += cv * cv;
            }
            #pragma unroll
            for (int o = 16; o > 0; o >>= 1) {
                dot += __shfl_down_sync(0xffffffffu, dot, o);
                sq  += __shfl_down_sync(0xffffffffu, sq, o);
            }
            if (lane == 0) sS[ci] = 2.0 * dot - sq;
        }
    }
    __syncthreads();
    if (tid == 0) {
        double best = -1e301; int bk = 1 << 30;
        #pragma unroll
        for (int j = 0; j < 32; j++) {
            double s = sS[j];
            int k = g_cand[(size_t)n * 32 + j];
            if (s > best || (s == best && k < bk)) { best = s; bk = k; }
        }
        sK = bk;
    }
    __syncthreads();

    const int k = sK;
    const int od = invD(tid);
    const float qv = cb[(size_t)k * DIM + od];
    const size_t off = (size_t)n * DIM + tid;
    const float rn = g_res[off] - qv;
    g_res[off] = rn;
    if (q == 0) g_acc[(size_t)n * DIM + od] = qv;
    else        g_acc[(size_t)n * DIM + od] += qv;

    float sq2 = rn * rn;
    #pragma unroll
    for (int o = 16; o > 0; o >>= 1) sq2 += __shfl_down_sync(0xffffffffu, sq2, o);
    if (lane == 0) red[w] = sq2;
    __syncthreads();
    if (tid == 0) {
        float tot = 0.0f;
        #pragma unroll
        for (int ww = 0; ww < 8; ww++) tot += red[ww];
        g_partial[q * NN + n] = tot;
        codes_out[q * NN + n] = (float)k;
    }
}

// ---------------- finalize: g_acc (N,D natural) -> out (B,D,T) ----------------
__global__ void rvq_finalize(float* __restrict__ out) {
    __shared__ float s[32][33];
    int b = blockIdx.z, d0 = blockIdx.y * 32, t0 = blockIdx.x * 32;
    int tx = threadIdx.x, ty = threadIdx.y;
    int t = t0 + ty;
    if (t < TT) s[ty][tx] = g_acc[((size_t)(b * TT + t)) * DIM + d0 + tx];
    __syncthreads();
    int t2 = t0 + tx;
    if (t2 < TT) out[((size_t)b * DIM + d0 + ty) * TT + t2] = s[tx][ty];
}

// ---------------- penalty ----------------
__global__ void rvq_penalty(float* __restrict__ out) {
    __shared__ float red[8];
    const int tid = threadIdx.x;
    float s = 0.0f;
    for (int i = tid; i < NQ * NN; i += 256) s += g_partial[i];
    #pragma unroll
    for (int o = 16; o > 0; o >>= 1) s += __shfl_down_sync(0xffffffffu, s, o);
    if ((tid & 31) == 0) red[tid >> 5] = s;
    __syncthreads();
    if (tid == 0) {
        float tot = 0.0f;
        #pragma unroll
        for (int w = 0; w < 8; w++) tot += red[w];
        out[(size_t)BB * DIM * TT + (size_t)NQ * NN] =
            tot / ((float)NQ * (float)NN * (float)DIM);
    }
}

// ---------------- launch ----------------
extern "C" void kernel_launch(void* const* d_in, const int* in_sizes, int n_in,
                              void* d_out, int out_size) {
    const float* x   = (const float*)d_in[0];
    const float* cbs = (const float*)d_in[1];
    float* out = (float*)d_out;
    float* codes_out = out + (size_t)BB * DIM * TT;

    cudaFuncSetAttribute(rvq_argmax_tc,
                         cudaFuncAttributeMaxDynamicSharedMemorySize, SMEM_BYTES);

    dim3 tb(32, 32);
    rvq_init<<<dim3(47, 8, 16), tb>>>(x);
    rvq_zero<<<64, 256>>>();
    rvq_cbsq<<<1024, 256>>>(cbs);
    rvq_cbperm<<<(NQ * BINS * DIM + 255) / 256, 256>>>(cbs);

    for (int q = 0; q < NQ; q++) {
        rvq_argmax_tc<<<NTILE * 2, 256, SMEM_BYTES>>>(q);
        rvq_select_update<<<NN, 256>>>(cbs, codes_out, q);
    }

    rvq_finalize<<<dim3(47, 8, 16), tb>>>(out);
    rvq_penalty<<<1, 256>>>(out);
}

// round 7
// speedup vs baseline: 1.1391x; 1.1391x over previous
#include <cuda_runtime.h>
#include <cuda_bf16.h>
#include <cstdint>
#include <float.h>

#define NQ    8
#define BINS  1024
#define DIM   256
#define BB    16
#define TT    1500
#define NN    (BB * TT)
#define NPAD  24064
#define NTILE 188

// device scratch
__device__ float g_res[NPAD * DIM];          // residual, D-permuted within 8-groups
__device__ float g_acc[NPAD * DIM];          // natural D order
__device__ float g_cbp[NQ * BINS * DIM];     // permuted codebook copy
__device__ int   g_cand[NPAD * 32];
__device__ float g_cand_s[NPAD * 32];
__device__ float g_cbsq[NQ * BINS];
__device__ float g_partial[NQ * NN];

// D permutation within each 8-group
__device__ __forceinline__ int permD(int o) { return (o & ~7) | ((o & 3) << 1) | ((o & 4) >> 2); }
__device__ __forceinline__ int invD(int p)  { return (p & ~7) | ((p & 1) << 2) | ((p & 6) >> 1); }

// ---------------- helpers ----------------
__device__ __forceinline__ uint32_t smem_u32(const void* p) {
    uint32_t a;
    asm("{ .reg .u64 t; cvta.to.shared.u64 t, %1; cvt.u32.u64 %0, t; }" : "=r"(a) : "l"(p));
    return a;
}
__device__ __forceinline__ void cp_async16(uint32_t dst, const void* src) {
    asm volatile("cp.async.cg.shared.global [%0], [%1], 16;" :: "r"(dst), "l"(src) : "memory");
}
#define CP_COMMIT() asm volatile("cp.async.commit_group;" ::: "memory")
#define CP_WAIT1()  asm volatile("cp.async.wait_group 1;" ::: "memory")

__device__ __forceinline__ void mma_tf32(float* c, const uint32_t* a, const uint32_t* b) {
    asm volatile(
        "mma.sync.aligned.m16n8k8.row.col.f32.tf32.tf32.f32 "
        "{%0,%1,%2,%3}, {%4,%5,%6,%7}, {%8,%9}, {%0,%1,%2,%3};"
        : "+f"(c[0]), "+f"(c[1]), "+f"(c[2]), "+f"(c[3])
        : "r"(a[0]), "r"(a[1]), "r"(a[2]), "r"(a[3]), "r"(b[0]), "r"(b[1]));
}

// smem floats: A[3][128][32] @0 (12288), B[3][128][32] @12288 (12288), cbsq[512] @24576
#define SA_OFF(s)   ((s) * 4096)
#define SB_OFF(s)   (12288 + (s) * 4096)
#define SQ(i)       (24576 + (i))
#define SMEM_BYTES  (25088 * 4)

// ---------------- init: x (B,D,T) -> g_res (N, permD); z==16 slice zeroes pad ----------------
__global__ void rvq_init(const float* __restrict__ x) {
    __shared__ float s[32][33];
    if (blockIdx.z == 16) {
        int idx = (blockIdx.y * 47 + blockIdx.x) * 1024 + threadIdx.y * 32 + threadIdx.x;
        if (idx < (NPAD - NN) * DIM) g_res[(size_t)NN * DIM + idx] = 0.0f;
        return;
    }
    int b = blockIdx.z, d0 = blockIdx.y * 32, t0 = blockIdx.x * 32;
    int tx = threadIdx.x, ty = threadIdx.y;
    int t = t0 + tx;
    if (t < TT) s[ty][tx] = x[((size_t)b * DIM + d0 + ty) * TT + t];
    __syncthreads();
    int t2 = t0 + ty;
    if (t2 < TT)
        g_res[((size_t)(b * TT + t2)) * DIM + d0 + permD(tx)] = s[tx][ty];
}

// ---------------- cbsq + permuted codebook copy ----------------
__global__ void rvq_cbsq(const float* __restrict__ cb) {
    int warp = (blockIdx.x * blockDim.x + threadIdx.x) >> 5;
    int lane = threadIdx.x & 31;
    if (warp >= NQ * BINS) return;
    const float* row = cb + (size_t)warp * DIM;
    float s = 0.0f;
    for (int d = lane; d < DIM; d += 32) { float c = row[d]; s += c * c; }
    #pragma unroll
    for (int o = 16; o > 0; o >>= 1) s += __shfl_down_sync(0xffffffffu, s, o);
    if (lane == 0) g_cbsq[warp] = s;
}

__global__ void rvq_cbperm(const float* __restrict__ cbs) {
    size_t i = (size_t)blockIdx.x * blockDim.x + threadIdx.x;
    if (i >= (size_t)NQ * BINS * DIM) return;
    int d = (int)(i & 255);
    g_cbp[(i - d) + permD(d)] = cbs[i];
}

// ---------------- tf32 tensor-core argmax: 128 rows x 512 bins per CTA ----------------
// chunks g = nt*8 + kc (nt 0..3 of 128 bins, kc 0..7 of K=32); 3-slot smem pipeline.
__global__ __launch_bounds__(256, 2) void rvq_argmax_tc(int q) {
    extern __shared__ float sm[];
    const uint32_t sb = smem_u32(sm);
    const int tid = threadIdx.x;
    const int lane = tid & 31, wid = tid >> 5;
    const int gid = lane >> 2, tg = lane & 3;
    const int wm = wid & 3, wn = wid >> 2;        // warp grid 4 (m) x 2 (n), warp tile 32x64
    const int mtile = blockIdx.x >> 1, half = blockIdx.x & 1;
    const int row0 = mtile * 128;
    const float* __restrict__ cbp = g_cbp + ((size_t)q * BINS + half * 512) * DIM;

    for (int i = tid; i < 512; i += 256) sm[SQ(i)] = g_cbsq[q * BINS + half * 512 + i];

    // prefetch mapping: thread handles rows ur+{0,32,64,96}, 16B unit useg
    const int ur = tid >> 3, useg = tid & 7;
    const float* aG = g_res + (size_t)(row0 + ur) * DIM + useg * 4;
    const float* bG = cbp + (size_t)ur * DIM + useg * 4;
    // swizzle unit is row-invariant (rows differ by 32): one word offset base
    const uint32_t wOff = (uint32_t)(ur * 32 + ((useg ^ (ur & 7)) << 2)) * 4u;

#define PREF(pg_) do { \
    const int slot_ = (pg_) % 3; \
    const uint32_t dA_ = sb + (uint32_t)SA_OFF(slot_) * 4u + wOff; \
    const uint32_t dB_ = sb + (uint32_t)SB_OFF(slot_) * 4u + wOff; \
    const float* sA_ = aG + ((pg_) & 7) * 32; \
    const float* sB_ = bG + (size_t)((pg_) >> 3) * 32768 + ((pg_) & 7) * 32; \
    _Pragma("unroll") \
    for (int i_ = 0; i_ < 4; i_++) { \
        cp_async16(dA_ + i_ * 4096u, sA_ + i_ * 8192); \
        cp_async16(dB_ + i_ * 4096u, sB_ + i_ * 8192); \
    } \
    CP_COMMIT(); \
} while (0)

    float ts[4][2]; int ti[4][2];
    #pragma unroll
    for (int s = 0; s < 4; s++) {
        ts[s][0] = -FLT_MAX; ts[s][1] = -FLT_MAX;
        ti[s][0] = 0; ti[s][1] = 0;
    }

    float c[2][8][4];
    #pragma unroll
    for (int mi = 0; mi < 2; mi++)
        #pragma unroll
        for (int ni = 0; ni < 8; ni++)
            #pragma unroll
            for (int v = 0; v < 4; v++) c[mi][ni][v] = 0.0f;

#define FOLD(slot, sc, kg) do { \
    if ((sc) > ts[slot][0]) { \
        ts[slot][1] = ts[slot][0]; ti[slot][1] = ti[slot][0]; \
        ts[slot][0] = (sc); ti[slot][0] = (kg); \
    } else if ((sc) > ts[slot][1]) { ts[slot][1] = (sc); ti[slot][1] = (kg); } \
} while (0)

    PREF(0);
    PREF(1);

    #pragma unroll 1
    for (int g = 0; g < 32; g++) {
        CP_WAIT1();            // chunk g landed (g+1 still pending)
        __syncthreads();       // visibility; slot (g+2)%3 fully consumed (iter g-1)
        if (g + 2 < 32) { PREF(g + 2); } else { CP_COMMIT(); }

        const int buf = g % 3;
        const uint32_t aBase = (uint32_t)SA_OFF(buf);
        const uint32_t bBase = (uint32_t)SB_OFF(buf);
        #pragma unroll
        for (int kk = 0; kk < 4; kk++) {
            const int colp = (((2 * kk + (tg >> 1)) ^ gid) << 2) + 2 * (tg & 1);
            uint32_t a[2][4];
            #pragma unroll
            for (int mi = 0; mi < 2; mi++) {
                int r = wm * 32 + mi * 16 + gid;
                float2 av0 = *(const float2*)&sm[aBase + r * 32 + colp];
                float2 av1 = *(const float2*)&sm[aBase + (r + 8) * 32 + colp];
                a[mi][0] = __float_as_uint(av0.x);
                a[mi][1] = __float_as_uint(av1.x);
                a[mi][2] = __float_as_uint(av0.y);
                a[mi][3] = __float_as_uint(av1.y);
            }
            #pragma unroll
            for (int ni = 0; ni < 8; ni++) {
                int n = wn * 64 + ni * 8 + gid;
                float2 bv = *(const float2*)&sm[bBase + n * 32 + colp];
                uint32_t b[2] = { __float_as_uint(bv.x), __float_as_uint(bv.y) };
                mma_tf32(c[0][ni], a[0], b);
                mma_tf32(c[1][ni], a[1], b);
            }
        }

        if ((g & 7) == 7) {
            const int nt = g >> 3;
            #pragma unroll
            for (int mi = 0; mi < 2; mi++)
                #pragma unroll
                for (int ni = 0; ni < 8; ni++) {
                    int cc = wn * 64 + ni * 8 + tg * 2;
                    int kl = nt * 128 + cc;
                    int kg = half * 512 + kl;
                    float q0 = sm[SQ(kl)], q1 = sm[SQ(kl + 1)];
                    float s0 = 2.0f * c[mi][ni][0] - q0;
                    float s1 = 2.0f * c[mi][ni][1] - q1;
                    float s2 = 2.0f * c[mi][ni][2] - q0;
                    float s3 = 2.0f * c[mi][ni][3] - q1;
                    FOLD(mi * 2 + 0, s0, kg);
                    FOLD(mi * 2 + 0, s1, kg + 1);
                    FOLD(mi * 2 + 1, s2, kg);
                    FOLD(mi * 2 + 1, s3, kg + 1);
                    #pragma unroll
                    for (int v = 0; v < 4; v++) c[mi][ni][v] = 0.0f;
                }
        }
    }

    // write 2 candidates per owned row (8 owners per row: wn x tg)
    const int owner = wn * 4 + tg;
    #pragma unroll
    for (int s = 0; s < 4; s++) {
        int row = row0 + wm * 32 + (s >> 1) * 16 + gid + (s & 1) * 8;
        size_t base = (size_t)row * 32 + half * 16 + owner * 2;
        g_cand[base]     = ti[s][0];  g_cand_s[base]     = ts[s][0];
        g_cand[base + 1] = ti[s][1];  g_cand_s[base + 1] = ts[s][1];
    }
}

// ---------------- exact select (fp64, margin-filtered) + update ----------------
__global__ void rvq_select_update(const float* __restrict__ cbs,
                                  float* __restrict__ codes_out, int q) {
    __shared__ float sApprox[32];
    __shared__ double sS[32];
    __shared__ int sK;
    __shared__ float red[8];
    __shared__ float sMax;
    const int n = blockIdx.x, tid = threadIdx.x;
    const int w = tid >> 5, lane = tid & 31;
    const float* __restrict__ cb = cbs + (size_t)q * BINS * DIM;

    if (tid < 32) {
        float a = g_cand_s[(size_t)n * 32 + tid];
        sApprox[tid] = a;
        sS[tid] = -1e300;
        #pragma unroll
        for (int o = 16; o > 0; o >>= 1) a = fmaxf(a, __shfl_down_sync(0xffffffffu, a, o));
        if (tid == 0) sMax = a;
    }
    __syncthreads();

    const float thr = sMax - 0.3f;
    #pragma unroll 1
    for (int c4 = 0; c4 < 4; c4++) {
        const int ci = w * 4 + c4;
        if (sApprox[ci] >= thr) {
            const int cand = g_cand[(size_t)n * 32 + ci];
            const float* r = g_res + (size_t)n * DIM;
            const float* c = cb + (size_t)cand * DIM;
            double dot = 0.0, sq = 0.0;
            #pragma unroll
            for (int d = lane; d < DIM; d += 32) {
                double rv = r[d], cv = c[invD(d)];
                dot += rv * cv; sq += cv * cv;
            }
            #pragma unroll
            for (int o = 16; o > 0; o >>= 1) {
                dot += __shfl_down_sync(0xffffffffu, dot, o);
                sq  += __shfl_down_sync(0xffffffffu, sq, o);
            }
            if (lane == 0) sS[ci] = 2.0 * dot - sq;
        }
    }
    __syncthreads();
    if (tid == 0) {
        double best = -1e301; int bk = 1 << 30;
        #pragma unroll
        for (int j = 0; j < 32; j++) {
            double s = sS[j];
            int k = g_cand[(size_t)n * 32 + j];
            if (s > best || (s == best && k < bk)) { best = s; bk = k; }
        }
        sK = bk;
    }
    __syncthreads();

    const int k = sK;
    const int od = invD(tid);
    const float qv = cb[(size_t)k * DIM + od];
    const size_t off = (size_t)n * DIM + tid;
    const float rn = g_res[off] - qv;
    g_res[off] = rn;
    if (q == 0) g_acc[(size_t)n * DIM + od] = qv;
    else        g_acc[(size_t)n * DIM + od] += qv;

    float sq2 = rn * rn;
    #pragma unroll
    for (int o = 16; o > 0; o >>= 1) sq2 += __shfl_down_sync(0xffffffffu, sq2, o);
    if (lane == 0) red[w] = sq2;
    __syncthreads();
    if (tid == 0) {
        float tot = 0.0f;
        #pragma unroll
        for (int ww = 0; ww < 8; ww++) tot += red[ww];
        g_partial[q * NN + n] = tot;
        codes_out[q * NN + n] = (float)k;
    }
}

// ---------------- finalize: g_acc (N,D natural) -> out (B,D,T) ----------------
__global__ void rvq_finalize(float* __restrict__ out) {
    __shared__ float s[32][33];
    int b = blockIdx.z, d0 = blockIdx.y * 32, t0 = blockIdx.x * 32;
    int tx = threadIdx.x, ty = threadIdx.y;
    int t = t0 + ty;
    if (t < TT) s[ty][tx] = g_acc[((size_t)(b * TT + t)) * DIM + d0 + tx];
    __syncthreads();
    int t2 = t0 + tx;
    if (t2 < TT) out[((size_t)b * DIM + d0 + ty) * TT + t2] = s[tx][ty];
}

// ---------------- penalty ----------------
__global__ void rvq_penalty(float* __restrict__ out) {
    __shared__ float red[8];
    const int tid = threadIdx.x;
    float s = 0.0f;
    for (int i = tid; i < NQ * NN; i += 256) s += g_partial[i];
    #pragma unroll
    for (int o = 16; o > 0; o >>= 1) s += __shfl_down_sync(0xffffffffu, s, o);
    if ((tid & 31) == 0) red[tid >> 5] = s;
    __syncthreads();
    if (tid == 0) {
        float tot = 0.0f;
        #pragma unroll
        for (int w = 0; w < 8; w++) tot += red[w];
        out[(size_t)BB * DIM * TT + (size_t)NQ * NN] =
            tot / ((float)NQ * (float)NN * (float)DIM);
    }
}

// ---------------- launch ----------------
extern "C" void kernel_launch(void* const* d_in, const int* in_sizes, int n_in,
                              void* d_out, int out_size) {
    const float* x   = (const float*)d_in[0];
    const float* cbs = (const float*)d_in[1];
    float* out = (float*)d_out;
    float* codes_out = out + (size_t)BB * DIM * TT;

    cudaFuncSetAttribute(rvq_argmax_tc,
                         cudaFuncAttributeMaxDynamicSharedMemorySize, SMEM_BYTES);

    dim3 tb(32, 32);
    rvq_init<<<dim3(47, 8, 17), tb>>>(x);
    rvq_cbsq<<<1024, 256>>>(cbs);
    rvq_cbperm<<<(NQ * BINS * DIM + 255) / 256, 256>>>(cbs);

    for (int q = 0; q < NQ; q++) {
        rvq_argmax_tc<<<NTILE * 2, 256, SMEM_BYTES>>>(q);
        rvq_select_update<<<NN, 256>>>(cbs, codes_out, q);
    }

    rvq_finalize<<<dim3(47, 8, 16), tb>>>(out);
    rvq_penalty<<<1, 256>>>(out);
}